// round 15
// baseline (speedup 1.0000x reference)
#include <cuda_runtime.h>
#include <cuda_bf16.h>
#include <cuda_fp16.h>
#include <cuda_fp8.h>
#include <cstdint>

// ---------------- problem dims ----------------
#define BQ 8
#define LQ 2048
#define MQ (BQ*LQ)      // 16384 tokens
#define MH (MQ/2)       // 8192 tokens per pipeline half
#define BH (BQ/2)       // 4 batches per half
#define DQ 512
#define EQ 1024
#define SQ 16
#define GQ 48

// GRU chunked scan
#define GRU_CHUNK 128
#define GRU_WARM  64
#define GRU_NC    (LQ/GRU_CHUNK)   // 16

// FP8 static scales (powers of 2)
#define SCALE_W   64.f
#define SCALE_XI  256.f
#define SCALE_XC  256.f
#define SCALE_YM  16384.f
#define INV0      (1.f/64.f)
#define INV1      (1.f/16384.f)
#define INV2      (1.f/1048576.f)

// ---------------- scratch ----------------
__device__ uint8_t       g_xn8[(size_t)MQ*DQ];
__device__ uint8_t       g_xin8[(size_t)MQ*EQ];
__device__ uint8_t       g_siluz8[(size_t)MQ*EQ];
__device__ uint8_t       g_xc8[(size_t)MQ*EQ];
__device__ float         g_xg[(size_t)MQ*GQ];
__device__ float         g_h[(size_t)MQ*SQ];
__device__ uint8_t       g_ymid8[(size_t)MQ*EQ];
__device__ uint8_t       g_wA8[2048*512];
__device__ uint8_t       g_wG8[128*1024];
__device__ uint8_t       g_wO8[512*1024];

// ---------------- helpers ----------------
__device__ __forceinline__ float tanh_fast(float x){
    float y; asm("tanh.approx.f32 %0, %1;" : "=f"(y) : "f"(x)); return y;
}
__device__ __forceinline__ float sigmoid_fast(float x){
    return fmaf(0.5f, tanh_fast(0.5f*x), 0.5f);
}
__device__ __forceinline__ float silu_fast(float x){ return x * sigmoid_fast(x); }

__device__ __forceinline__ unsigned short pk8(float a, float b){
    return (unsigned short)__nv_cvt_float2_to_fp8x2(make_float2(a,b), __NV_SATFINITE, __NV_E4M3);
}
__device__ __forceinline__ float2 up8(unsigned short v){
    __half2_raw hr = __nv_cvt_fp8x2_to_halfraw2((__nv_fp8x2_storage_t)v, __NV_E4M3);
    __half2 h = *reinterpret_cast<__half2*>(&hr);
    return __half22float2(h);
}
__device__ __forceinline__ void up8x4(unsigned w, float* f){
    float2 a = up8((unsigned short)(w & 0xffffu));
    float2 b = up8((unsigned short)(w >> 16));
    f[0]=a.x; f[1]=a.y; f[2]=b.x; f[3]=b.y;
}

__device__ __forceinline__ unsigned smem_u32(const void* p){
    return (unsigned)__cvta_generic_to_shared(p);
}
__device__ __forceinline__ void ldm_x4(unsigned& r0, unsigned& r1, unsigned& r2, unsigned& r3, unsigned a){
    asm volatile("ldmatrix.sync.aligned.m8n8.x4.shared.b16 {%0,%1,%2,%3}, [%4];"
        : "=r"(r0),"=r"(r1),"=r"(r2),"=r"(r3) : "r"(a));
}
__device__ __forceinline__ void ldm_x2(unsigned& r0, unsigned& r1, unsigned a){
    asm volatile("ldmatrix.sync.aligned.m8n8.x2.shared.b16 {%0,%1}, [%2];"
        : "=r"(r0),"=r"(r1) : "r"(a));
}
__device__ __forceinline__ void mma_fp8_h(unsigned c[2], unsigned a0,unsigned a1,unsigned a2,unsigned a3,
                                          unsigned b0, unsigned b1){
    asm volatile("mma.sync.aligned.m16n8k32.row.col.f16.e4m3.e4m3.f16 "
        "{%0,%1}, {%2,%3,%4,%5}, {%6,%7}, {%0,%1};"
        : "+r"(c[0]),"+r"(c[1])
        : "r"(a0),"r"(a1),"r"(a2),"r"(a3),"r"(b0),"r"(b1));
}
__device__ __forceinline__ void cp16(unsigned sdst, const void* gsrc){
    asm volatile("cp.async.cg.shared.global [%0], [%1], 16;" :: "r"(sdst), "l"(gsrc));
}
__device__ __forceinline__ void cp_commit(){ asm volatile("cp.async.commit_group;" ::: "memory"); }
__device__ __forceinline__ void cp_wait1(){ asm volatile("cp.async.wait_group 1;" ::: "memory"); }

// ---------------- weight conversion: fp32 -> e4m3 x64 ----------------
__global__ __launch_bounds__(256) void k_convert_all(const float* __restrict__ wa,
                                                     const float* __restrict__ wg,
                                                     const float* __restrict__ wo){
    const int NA4 = (2048*512)/4, NG4 = (128*1024)/4, NO4 = (512*1024)/4;
    int i = blockIdx.x*blockDim.x + threadIdx.x;
    float4 v; uint8_t* dst;
    if (i < NA4){
        v = __ldg((const float4*)wa + i);
        dst = g_wA8 + 4*(size_t)i;
    } else if (i < NA4 + NG4){
        int j = i - NA4;
        if (4*j < 48*1024) v = __ldg((const float4*)wg + j);
        else { v.x=v.y=v.z=v.w=0.f; }
        dst = g_wG8 + 4*(size_t)j;
    } else if (i < NA4 + NG4 + NO4){
        int j = i - NA4 - NG4;
        v = __ldg((const float4*)wo + j);
        dst = g_wO8 + 4*(size_t)j;
    } else return;
    unsigned short s0 = pk8(v.x*SCALE_W, v.y*SCALE_W);
    unsigned short s1 = pk8(v.z*SCALE_W, v.w*SCALE_W);
    *(unsigned*)dst = (unsigned)s0 | ((unsigned)s1 << 16);
}

// ---------------- LayerNorm -> e4m3 (half, offset mOff tokens) ----------------
__global__ __launch_bounds__(128) void k_ln(const float* __restrict__ x,
                                            const float* __restrict__ w,
                                            const float* __restrict__ bb,
                                            int mOff){
    int row = mOff + blockIdx.x;
    int tid = threadIdx.x;
    const float4* xr = (const float4*)(x + (size_t)row*DQ);
    float4 v = xr[tid];
    float s  = v.x + v.y + v.z + v.w;
    float ss = fmaf(v.x,v.x, fmaf(v.y,v.y, fmaf(v.z,v.z, v.w*v.w)));
    #pragma unroll
    for (int o=16;o;o>>=1){ s += __shfl_xor_sync(~0u,s,o); ss += __shfl_xor_sync(~0u,ss,o); }
    __shared__ float rs[4], rss[4];
    __shared__ float smu, srstd;
    int wid = tid>>5;
    if ((tid&31)==0){ rs[wid]=s; rss[wid]=ss; }
    __syncthreads();
    if (tid==0){
        float S = rs[0]+rs[1]+rs[2]+rs[3];
        float SS= rss[0]+rss[1]+rss[2]+rss[3];
        float mu = S * (1.f/512.f);
        float var = SS * (1.f/512.f) - mu*mu;
        smu = mu; srstd = rsqrtf(var + 1e-5f);
    }
    __syncthreads();
    float mu = smu, rstd = srstd;
    float4 w4 = ((const float4*)w)[tid];
    float4 b4 = ((const float4*)bb)[tid];
    float y0 = fmaf((v.x-mu)*rstd, w4.x, b4.x);
    float y1 = fmaf((v.y-mu)*rstd, w4.y, b4.y);
    float y2 = fmaf((v.z-mu)*rstd, w4.z, b4.z);
    float y3 = fmaf((v.w-mu)*rstd, w4.w, b4.w);
    unsigned short s0 = pk8(y0, y1);
    unsigned short s1 = pk8(y2, y3);
    ((unsigned*)g_xn8)[(size_t)row*128 + tid] = (unsigned)s0 | ((unsigned)s1 << 16);
}

// ---------------- fp8 mma GEMM (f16 accum), 64-row tiles, 256 thr, occ 3 ----------------
// MODE 0: in_proj (N=2048)   MODE 1: gru_ih   MODE 2: out_proj
#define GSTG 3
#define GROWB 80

template<int MODE, int MT, int NT>
__global__ __launch_bounds__(256,3) void k_gemm(const float* __restrict__ bias,
                                                const float* __restrict__ resid,
                                                float* __restrict__ outf,
                                                int mOff){
    const uint8_t* __restrict__ A;
    const uint8_t* __restrict__ Bw;
    constexpr int K = (MODE==0) ? 512 : 1024;
    if constexpr (MODE==0){ A = g_xn8;   Bw = g_wA8; }
    if constexpr (MODE==1){ A = g_xc8;   Bw = g_wG8; }
    if constexpr (MODE==2){ A = g_ymid8; Bw = g_wO8; }

    constexpr int ASTG_B = MT*GROWB;
    constexpr int STG    = (MT+NT)*GROWB;
    constexpr int NMT = MT/32;
    constexpr int NNT = NT/32;

    extern __shared__ __align__(16) uint8_t dynsm[];
    const unsigned dsm = smem_u32(dynsm);

    const int tid  = threadIdx.x;
    const int lane = tid & 31, warp = tid >> 5;
    const int wm = warp >> 2, wn = warp & 3;
    const int mBlk = mOff + blockIdx.y * MT, nBlk = blockIdx.x * NT;

    unsigned acc[NMT][NNT][2];
    #pragma unroll
    for (int mt=0;mt<NMT;mt++)
        #pragma unroll
        for (int nt=0;nt<NNT;nt++){ acc[mt][nt][0]=0u; acc[mt][nt][1]=0u; }

    constexpr int nKB = K >> 6;
    const int lrow = tid >> 2;
    const int lch  = tid & 3;

    auto prefetch = [&](int kb, int s){
        const int ko = kb*64;
        const unsigned base = dsm + s*STG;
        #pragma unroll
        for (int j=0;j<MT/64;j++){
            int row = lrow + 64*j;
            cp16(base + row*GROWB + lch*16, A + (size_t)(mBlk+row)*K + ko + lch*16);
        }
        #pragma unroll
        for (int j=0;j<NT/64;j++){
            int row = lrow + 64*j;
            cp16(base + ASTG_B + row*GROWB + lch*16, Bw + (size_t)(nBlk+row)*K + ko + lch*16);
        }
        cp_commit();
    };

    prefetch(0, 0);
    prefetch(1, 1);

    int s = 0;
    for (int kb = 0; kb < nKB; kb++){
        cp_wait1();
        __syncthreads();
        int pf = kb + 2;
        if (pf < nKB){
            int sp = s + 2; if (sp >= GSTG) sp -= GSTG;
            prefetch(pf, sp);
        } else {
            cp_commit();
        }

        const unsigned Ab = dsm + s*STG;
        const unsigned Bb = Ab + ASTG_B;
        #pragma unroll
        for (int ks=0;ks<2;ks++){
            unsigned a[NMT][4], b[NNT][2];
            #pragma unroll
            for (int mt=0;mt<NMT;mt++){
                unsigned addr = Ab + (wm*(MT/2) + mt*16 + (lane&15))*GROWB + ks*32 + (lane>>4)*16;
                ldm_x4(a[mt][0],a[mt][1],a[mt][2],a[mt][3], addr);
            }
            #pragma unroll
            for (int nt=0;nt<NNT;nt++){
                unsigned addr = Bb + (wn*(NT/4) + nt*8 + (lane&7))*GROWB + ks*32 + ((lane>>3)&1)*16;
                ldm_x2(b[nt][0],b[nt][1], addr);
            }
            #pragma unroll
            for (int mt=0;mt<NMT;mt++)
                #pragma unroll
                for (int nt=0;nt<NNT;nt++)
                    mma_fp8_h(acc[mt][nt], a[mt][0],a[mt][1],a[mt][2],a[mt][3], b[nt][0],b[nt][1]);
        }
        s = (s==GSTG-1) ? 0 : s+1;
    }

    // epilogue
    #pragma unroll
    for (int mt=0;mt<NMT;mt++){
        #pragma unroll
        for (int nt=0;nt<NNT;nt++){
            int rowb = mBlk + wm*(MT/2) + mt*16 + (lane>>2);
            int col  = nBlk + wn*(NT/4) + nt*8 + (lane&3)*2;
            #pragma unroll
            for (int half=0; half<2; half++){
                int r = rowb + half*8;
                __half2 hv = *reinterpret_cast<__half2*>(&acc[mt][nt][half]);
                float v0 = __low2float(hv), v1 = __high2float(hv);
                if constexpr (MODE==0){
                    v0 = fmaf(v0, INV0, __ldg(bias + col));
                    v1 = fmaf(v1, INV0, __ldg(bias + col + 1));
                    if (col < 1024){
                        *(unsigned short*)&g_xin8[(size_t)r*1024 + col] =
                            pk8(v0*SCALE_XI, v1*SCALE_XI);
                    } else {
                        *(unsigned short*)&g_siluz8[(size_t)r*1024 + col-1024] =
                            pk8(silu_fast(v0)*SCALE_XI, silu_fast(v1)*SCALE_XI);
                    }
                }
                if constexpr (MODE==1){
                    if (col < GQ){
                        g_xg[(size_t)r*GQ + col]   = fmaf(v0, INV1, __ldg(bias + col));
                        g_xg[(size_t)r*GQ + col+1] = fmaf(v1, INV1, __ldg(bias + col + 1));
                    }
                }
                if constexpr (MODE==2){
                    size_t o = (size_t)r*512 + col;
                    float2 rr = *(const float2*)&resid[o];
                    float2 ov;
                    ov.x = fmaf(v0, INV2, __ldg(bias + col))     + rr.x;
                    ov.y = fmaf(v1, INV2, __ldg(bias + col + 1)) + rr.y;
                    *(float2*)&outf[o] = ov;
                }
            }
        }
    }
}

// ---------------- depthwise conv1d (k=3, pad=1) + SiLU, half grid ----------------
__global__ __launch_bounds__(256) void k_conv(const float* __restrict__ cw, const float* __restrict__ cb,
                                              int mOff){
    const int tid = threadIdx.x;
    const int g = tid & 127;
    const int e0 = g*8;
    float wreg[24]; float breg[8];
    {
        const float4* wp = (const float4*)(cw + e0*3);
        #pragma unroll
        for (int j=0;j<6;j++){
            float4 t = __ldg(wp + j);
            wreg[4*j]  =t.x*(1.f/SCALE_XI); wreg[4*j+1]=t.y*(1.f/SCALE_XI);
            wreg[4*j+2]=t.z*(1.f/SCALE_XI); wreg[4*j+3]=t.w*(1.f/SCALE_XI);
        }
        const float4* bp = (const float4*)(cb + e0);
        float4 t0 = __ldg(bp), t1 = __ldg(bp+1);
        breg[0]=t0.x;breg[1]=t0.y;breg[2]=t0.z;breg[3]=t0.w;
        breg[4]=t1.x;breg[5]=t1.y;breg[6]=t1.z;breg[7]=t1.w;
    }
    const uint2* base = (const uint2*)g_xin8;
    uint2 zz; zz.x=zz.y=0u;

    #pragma unroll
    for (int it=0; it<8; it++){
        int v = blockIdx.x*2048 + it*256 + tid;     // local id within half
        int m = mOff + (v >> 7);
        int l = m & (LQ-1);
        size_t idx = (size_t)m*128 + g;
        uint2 mid2 = base[idx];
        uint2 lf2 = (l > 0)      ? base[idx-128] : zz;
        uint2 rt2 = (l < LQ-1)   ? base[idx+128] : zz;

        float fm[8], fl[8], fr[8];
        up8x4(mid2.x, fm); up8x4(mid2.y, fm+4);
        up8x4(lf2.x,  fl); up8x4(lf2.y,  fl+4);
        up8x4(rt2.x,  fr); up8x4(rt2.y,  fr+4);

        unsigned short outp[4];
        #pragma unroll
        for (int j=0;j<4;j++){
            int jj = 2*j;
            float val0 = fmaf(wreg[jj*3+0], fl[jj],   fmaf(wreg[jj*3+1], fm[jj],   fmaf(wreg[jj*3+2], fr[jj],   breg[jj])));
            float val1 = fmaf(wreg[jj*3+3], fl[jj+1], fmaf(wreg[jj*3+4], fm[jj+1], fmaf(wreg[jj*3+5], fr[jj+1], breg[jj+1])));
            outp[j] = pk8(silu_fast(val0)*SCALE_XC, silu_fast(val1)*SCALE_XC);
        }
        uint2 pack; pack.x = (unsigned)outp[0] | ((unsigned)outp[1]<<16);
        pack.y = (unsigned)outp[2] | ((unsigned)outp[3]<<16);
        *(uint2*)&g_xc8[(size_t)m*EQ + e0] = pack;
    }
}

// ---------------- GRU: chunked-parallel scan (per-batch offset) ----------------
__device__ __forceinline__ float dot16(const float (&w)[16], const float (&h)[16]){
    float a0=0.f,a1=0.f,a2=0.f,a3=0.f,a4=0.f,a5=0.f,a6=0.f,a7=0.f;
    a0=fmaf(w[0],h[0],a0);   a1=fmaf(w[1],h[1],a1);   a2=fmaf(w[2],h[2],a2);   a3=fmaf(w[3],h[3],a3);
    a4=fmaf(w[4],h[4],a4);   a5=fmaf(w[5],h[5],a5);   a6=fmaf(w[6],h[6],a6);   a7=fmaf(w[7],h[7],a7);
    a0=fmaf(w[8],h[8],a0);   a1=fmaf(w[9],h[9],a1);   a2=fmaf(w[10],h[10],a2); a3=fmaf(w[11],h[11],a3);
    a4=fmaf(w[12],h[12],a4); a5=fmaf(w[13],h[13],a5); a6=fmaf(w[14],h[14],a6); a7=fmaf(w[15],h[15],a7);
    return ((a0+a1)+(a2+a3)) + ((a4+a5)+(a6+a7));
}

__global__ __launch_bounds__(32) void k_gru(const float* __restrict__ Whh,
                                            const float* __restrict__ bhh,
                                            int bOff){
    const int b = bOff + blockIdx.x;
    const int c = blockIdx.y;
    const int lane = threadIdx.x;
    __shared__ float sh[32*GQ];

    float Wr[16], Wz[16], Wn[16];
    float br=0.f, bz=0.f, bn=0.f;
    if (lane < 16){
        #pragma unroll
        for (int k=0;k<16;k++){
            Wr[k] = Whh[lane*16 + k];
            Wz[k] = Whh[(16+lane)*16 + k];
            Wn[k] = Whh[(32+lane)*16 + k];
        }
        br = bhh[lane]; bz = bhh[16+lane]; bn = bhh[32+lane];
    } else {
        #pragma unroll
        for (int k=0;k<16;k++){ Wr[k]=0.f; Wz[k]=0.f; Wn[k]=0.f; }
    }

    float h[16];
    #pragma unroll
    for (int k=0;k<16;k++) h[k] = 0.f;
    float hi = 0.f;

    const int start  = c * GRU_CHUNK;
    const int wstart = (c == 0) ? 0 : (start - GRU_WARM);
    const int nsteps = (start + GRU_CHUNK) - wstart;
    const int n32    = nsteps >> 5;

    const float* xb = g_xg + ((size_t)b*LQ + wstart) * GQ;
    float*       hb = g_h  + (size_t)b*LQ*SQ;

    for (int j = 0; j < n32; j++){
        __syncwarp();
        const float4* src = (const float4*)(xb + (size_t)j*32*GQ);
        float4* dst = (float4*)sh;
        #pragma unroll
        for (int q=0;q<12;q++) dst[lane + 32*q] = src[lane + 32*q];
        __syncwarp();
        #pragma unroll 4
        for (int t=0;t<32;t++){
            const float* sp = sh + t*GQ;
            float xr=0.f, xz=0.f, xn=0.f;
            if (lane < 16){ xr = sp[lane]; xz = sp[16+lane]; xn = sp[32+lane]; }
            float hr = dot16(Wr, h) + br;
            float hz = dot16(Wz, h) + bz;
            float hn = dot16(Wn, h) + bn;
            float r  = sigmoid_fast(xr + hr);
            float z  = sigmoid_fast(xz + hz);
            float n  = tanh_fast(fmaf(r, hn, xn));
            float hnew = fmaf(z, hi - n, n);
            #pragma unroll
            for (int k=0;k<16;k++) h[k] = __shfl_sync(0xffffffffu, hnew, k);
            hi = hnew;
            int tg = wstart + j*32 + t;
            if (lane < 16 && tg >= start) hb[(size_t)tg*SQ + lane] = hnew;
        }
    }
}

// ---------------- ssm_proj (K=16) + gate by silu(z) -> e4m3, half grid ----------------
__global__ __launch_bounds__(256) void k_ssm(const float* __restrict__ W, const float* __restrict__ bias,
                                             int mOff){
    int v = blockIdx.x*blockDim.x + threadIdx.x;
    if (v >= MH*(EQ/8)) return;
    int e8 = v & 127;
    int m  = mOff + (v >> 7);
    int e0 = e8*8;

    float h[16];
    {
        const float4* hv = (const float4*)(g_h + (size_t)m*SQ);
        #pragma unroll
        for (int j=0;j<4;j++){
            float4 t = __ldg(hv + j);
            h[4*j]=t.x; h[4*j+1]=t.y; h[4*j+2]=t.z; h[4*j+3]=t.w;
        }
    }
    uint2 sz2 = *(const uint2*)&g_siluz8[(size_t)m*EQ + e0];
    float szf[8];
    up8x4(sz2.x, szf); up8x4(sz2.y, szf+4);

    unsigned short outp[4];
    #pragma unroll
    for (int j=0;j<4;j++){
        float o[2];
        #pragma unroll
        for (int q=0;q<2;q++){
            int e = e0 + 2*j + q;
            const float4* wr = (const float4*)(W + (size_t)e*SQ);
            float acc = __ldg(bias + e);
            #pragma unroll
            for (int p=0;p<4;p++){
                float4 w4 = __ldg(wr + p);
                acc = fmaf(w4.x, h[4*p],   acc);
                acc = fmaf(w4.y, h[4*p+1], acc);
                acc = fmaf(w4.z, h[4*p+2], acc);
                acc = fmaf(w4.w, h[4*p+3], acc);
            }
            o[q] = acc;
        }
        outp[j] = pk8(o[0]*szf[2*j]*(SCALE_YM/SCALE_XI), o[1]*szf[2*j+1]*(SCALE_YM/SCALE_XI));
    }
    uint2 pack; pack.x = (unsigned)outp[0] | ((unsigned)outp[1]<<16);
    pack.y = (unsigned)outp[2] | ((unsigned)outp[3]<<16);
    *(uint2*)&g_ymid8[(size_t)m*EQ + e0] = pack;
}

// ---------------- launch: staggered two-half pipeline ----------------
extern "C" void kernel_launch(void* const* d_in, const int* in_sizes, int n_in,
                              void* d_out, int out_size){
    const float* x        = (const float*)d_in[0];
    const float* norm_w   = (const float*)d_in[1];
    const float* norm_b   = (const float*)d_in[2];
    const float* in_proj_w= (const float*)d_in[3];
    const float* in_proj_b= (const float*)d_in[4];
    const float* conv_w   = (const float*)d_in[5];
    const float* conv_b   = (const float*)d_in[6];
    const float* gru_w_ih = (const float*)d_in[7];
    const float* gru_w_hh = (const float*)d_in[8];
    const float* gru_b_ih = (const float*)d_in[9];
    const float* gru_b_hh = (const float*)d_in[10];
    const float* ssm_w    = (const float*)d_in[11];
    const float* ssm_b    = (const float*)d_in[12];
    const float* out_w    = (const float*)d_in[13];
    const float* out_b    = (const float*)d_in[14];
    float* out = (float*)d_out;

    const int SM0 = GSTG*(64+128)*GROWB;   // 46080
    const int SM1 = GSTG*(64+64)*GROWB;    // 30720
    const int SM2 = GSTG*(64+128)*GROWB;   // 46080

    static cudaStream_t s1 = nullptr;
    static cudaEvent_t evF = nullptr, evG0 = nullptr, evJ = nullptr;
    static bool init_done = false;
    if (!init_done){
        cudaFuncSetAttribute(k_gemm<0,64,128>, cudaFuncAttributeMaxDynamicSharedMemorySize, SM0);
        cudaFuncSetAttribute(k_gemm<1,64,64>,  cudaFuncAttributeMaxDynamicSharedMemorySize, SM1);
        cudaFuncSetAttribute(k_gemm<2,64,128>, cudaFuncAttributeMaxDynamicSharedMemorySize, SM2);
        cudaStreamCreateWithFlags(&s1, cudaStreamNonBlocking);
        cudaEventCreateWithFlags(&evF,  cudaEventDisableTiming);
        cudaEventCreateWithFlags(&evG0, cudaEventDisableTiming);
        cudaEventCreateWithFlags(&evJ,  cudaEventDisableTiming);
        init_done = true;
    }

    const int NCVT4 = (2048*512 + 128*1024 + 512*1024)/4;
    k_convert_all<<<(NCVT4+255)/256, 256>>>(in_proj_w, gru_w_ih, out_w);

    // fork side stream
    cudaEventRecord(evF, 0);
    cudaStreamWaitEvent(s1, evF, 0);

    // half-1 LN can run immediately (tiny, overlaps half-0 LN/G0 start)
    k_ln<<<MH, 128, 0, s1>>>(x, norm_w, norm_b, MH);

    // ---- half 0: LN -> G0 ----
    k_ln<<<MH, 128>>>(x, norm_w, norm_b, 0);
    k_gemm<0,64,128><<<dim3(2048/128, MH/64), 256, SM0>>>(in_proj_b, nullptr, nullptr, 0);
    cudaEventRecord(evG0, 0);              // stagger point

    // half-1 G0 waits for half-0 G0 -> runs concurrent with half-0's tail
    cudaStreamWaitEvent(s1, evG0, 0);
    k_gemm<0,64,128><<<dim3(2048/128, MH/64), 256, SM0, s1>>>(in_proj_b, nullptr, nullptr, MH);

    // ---- half 0 tail + G2 (main) ----
    k_conv<<<512, 256>>>(conv_w, conv_b, 0);
    k_gemm<1,64,64><<<dim3(1, MH/64), 256, SM1>>>(gru_b_ih, nullptr, nullptr, 0);
    k_gru<<<dim3(BH, GRU_NC), 32>>>(gru_w_hh, gru_b_hh, 0);
    k_ssm<<<(MH*(EQ/8)+255)/256, 256>>>(ssm_w, ssm_b, 0);
    k_gemm<2,64,128><<<dim3(512/128, MH/64), 256, SM2>>>(out_b, x, out, 0);

    // ---- half 1 tail + G2 (side stream) ----
    k_conv<<<512, 256, 0, s1>>>(conv_w, conv_b, MH);
    k_gemm<1,64,64><<<dim3(1, MH/64), 256, SM1, s1>>>(gru_b_ih, nullptr, nullptr, MH);
    k_gru<<<dim3(BH, GRU_NC), 32, 0, s1>>>(gru_w_hh, gru_b_hh, BH);
    k_ssm<<<(MH*(EQ/8)+255)/256, 256, 0, s1>>>(ssm_w, ssm_b, MH);
    k_gemm<2,64,128><<<dim3(512/128, MH/64), 256, SM2, s1>>>(out_b, x, out, MH);

    // join
    cudaEventRecord(evJ, s1);
    cudaStreamWaitEvent(0, evJ, 0);
}

// round 16
// speedup vs baseline: 1.0242x; 1.0242x over previous
#include <cuda_runtime.h>
#include <cuda_bf16.h>
#include <cuda_fp16.h>
#include <cuda_fp8.h>
#include <cstdint>

// ---------------- problem dims ----------------
#define BQ 8
#define LQ 2048
#define MQ (BQ*LQ)      // 16384 tokens
#define MH (MQ/2)       // 8192 tokens per pipeline half
#define BH (BQ/2)       // 4 batches per half
#define DQ 512
#define EQ 1024
#define SQ 16
#define GQ 48

// GRU chunked scan
#define GRU_CHUNK 128
#define GRU_WARM  64
#define GRU_NC    (LQ/GRU_CHUNK)   // 16

// FP8 static scales (powers of 2)
#define SCALE_W   64.f
#define SCALE_XI  256.f
#define SCALE_XC  256.f
#define SCALE_YM  16384.f
#define INV0      (1.f/64.f)
#define INV1      (1.f/16384.f)
#define INV2      (1.f/1048576.f)

// ---------------- scratch ----------------
__device__ uint8_t       g_xn8[(size_t)MQ*DQ];
__device__ uint8_t       g_xin8[(size_t)MQ*EQ];
__device__ uint8_t       g_siluz8[(size_t)MQ*EQ];
__device__ uint8_t       g_xc8[(size_t)MQ*EQ];
__device__ float         g_xg[(size_t)MQ*GQ];
__device__ float         g_h[(size_t)MQ*SQ];
__device__ uint8_t       g_ymid8[(size_t)MQ*EQ];
__device__ uint8_t       g_wA8[2048*512];
__device__ uint8_t       g_wG8[128*1024];
__device__ uint8_t       g_wO8[512*1024];

// ---------------- helpers ----------------
__device__ __forceinline__ float tanh_fast(float x){
    float y; asm("tanh.approx.f32 %0, %1;" : "=f"(y) : "f"(x)); return y;
}
__device__ __forceinline__ float sigmoid_fast(float x){
    return fmaf(0.5f, tanh_fast(0.5f*x), 0.5f);
}
__device__ __forceinline__ float silu_fast(float x){ return x * sigmoid_fast(x); }

__device__ __forceinline__ unsigned short pk8(float a, float b){
    return (unsigned short)__nv_cvt_float2_to_fp8x2(make_float2(a,b), __NV_SATFINITE, __NV_E4M3);
}
__device__ __forceinline__ float2 up8(unsigned short v){
    __half2_raw hr = __nv_cvt_fp8x2_to_halfraw2((__nv_fp8x2_storage_t)v, __NV_E4M3);
    __half2 h = *reinterpret_cast<__half2*>(&hr);
    return __half22float2(h);
}
__device__ __forceinline__ void up8x4(unsigned w, float* f){
    float2 a = up8((unsigned short)(w & 0xffffu));
    float2 b = up8((unsigned short)(w >> 16));
    f[0]=a.x; f[1]=a.y; f[2]=b.x; f[3]=b.y;
}

__device__ __forceinline__ unsigned smem_u32(const void* p){
    return (unsigned)__cvta_generic_to_shared(p);
}
__device__ __forceinline__ void ldm_x4(unsigned& r0, unsigned& r1, unsigned& r2, unsigned& r3, unsigned a){
    asm volatile("ldmatrix.sync.aligned.m8n8.x4.shared.b16 {%0,%1,%2,%3}, [%4];"
        : "=r"(r0),"=r"(r1),"=r"(r2),"=r"(r3) : "r"(a));
}
__device__ __forceinline__ void ldm_x2(unsigned& r0, unsigned& r1, unsigned a){
    asm volatile("ldmatrix.sync.aligned.m8n8.x2.shared.b16 {%0,%1}, [%2];"
        : "=r"(r0),"=r"(r1) : "r"(a));
}
__device__ __forceinline__ void mma_fp8_h(unsigned c[2], unsigned a0,unsigned a1,unsigned a2,unsigned a3,
                                          unsigned b0, unsigned b1){
    asm volatile("mma.sync.aligned.m16n8k32.row.col.f16.e4m3.e4m3.f16 "
        "{%0,%1}, {%2,%3,%4,%5}, {%6,%7}, {%0,%1};"
        : "+r"(c[0]),"+r"(c[1])
        : "r"(a0),"r"(a1),"r"(a2),"r"(a3),"r"(b0),"r"(b1));
}
__device__ __forceinline__ void cp16(unsigned sdst, const void* gsrc){
    asm volatile("cp.async.cg.shared.global [%0], [%1], 16;" :: "r"(sdst), "l"(gsrc));
}
__device__ __forceinline__ void cp_commit(){ asm volatile("cp.async.commit_group;" ::: "memory"); }
__device__ __forceinline__ void cp_wait2(){ asm volatile("cp.async.wait_group 2;" ::: "memory"); }

// ---------------- weight conversion: fp32 -> e4m3 x64 ----------------
__global__ __launch_bounds__(256) void k_convert_all(const float* __restrict__ wa,
                                                     const float* __restrict__ wg,
                                                     const float* __restrict__ wo){
    const int NA4 = (2048*512)/4, NG4 = (128*1024)/4, NO4 = (512*1024)/4;
    int i = blockIdx.x*blockDim.x + threadIdx.x;
    float4 v; uint8_t* dst;
    if (i < NA4){
        v = __ldg((const float4*)wa + i);
        dst = g_wA8 + 4*(size_t)i;
    } else if (i < NA4 + NG4){
        int j = i - NA4;
        if (4*j < 48*1024) v = __ldg((const float4*)wg + j);
        else { v.x=v.y=v.z=v.w=0.f; }
        dst = g_wG8 + 4*(size_t)j;
    } else if (i < NA4 + NG4 + NO4){
        int j = i - NA4 - NG4;
        v = __ldg((const float4*)wo + j);
        dst = g_wO8 + 4*(size_t)j;
    } else return;
    unsigned short s0 = pk8(v.x*SCALE_W, v.y*SCALE_W);
    unsigned short s1 = pk8(v.z*SCALE_W, v.w*SCALE_W);
    *(unsigned*)dst = (unsigned)s0 | ((unsigned)s1 << 16);
}

// ---------------- LayerNorm -> e4m3 (half, offset mOff tokens) ----------------
__global__ __launch_bounds__(128) void k_ln(const float* __restrict__ x,
                                            const float* __restrict__ w,
                                            const float* __restrict__ bb,
                                            int mOff){
    int row = mOff + blockIdx.x;
    int tid = threadIdx.x;
    const float4* xr = (const float4*)(x + (size_t)row*DQ);
    float4 v = xr[tid];
    float s  = v.x + v.y + v.z + v.w;
    float ss = fmaf(v.x,v.x, fmaf(v.y,v.y, fmaf(v.z,v.z, v.w*v.w)));
    #pragma unroll
    for (int o=16;o;o>>=1){ s += __shfl_xor_sync(~0u,s,o); ss += __shfl_xor_sync(~0u,ss,o); }
    __shared__ float rs[4], rss[4];
    __shared__ float smu, srstd;
    int wid = tid>>5;
    if ((tid&31)==0){ rs[wid]=s; rss[wid]=ss; }
    __syncthreads();
    if (tid==0){
        float S = rs[0]+rs[1]+rs[2]+rs[3];
        float SS= rss[0]+rss[1]+rss[2]+rss[3];
        float mu = S * (1.f/512.f);
        float var = SS * (1.f/512.f) - mu*mu;
        smu = mu; srstd = rsqrtf(var + 1e-5f);
    }
    __syncthreads();
    float mu = smu, rstd = srstd;
    float4 w4 = ((const float4*)w)[tid];
    float4 b4 = ((const float4*)bb)[tid];
    float y0 = fmaf((v.x-mu)*rstd, w4.x, b4.x);
    float y1 = fmaf((v.y-mu)*rstd, w4.y, b4.y);
    float y2 = fmaf((v.z-mu)*rstd, w4.z, b4.z);
    float y3 = fmaf((v.w-mu)*rstd, w4.w, b4.w);
    unsigned short s0 = pk8(y0, y1);
    unsigned short s1 = pk8(y2, y3);
    ((unsigned*)g_xn8)[(size_t)row*128 + tid] = (unsigned)s0 | ((unsigned)s1 << 16);
}

// ---------------- fp8 mma GEMM (f16 accum), 64-row tiles, 4-stage ring, wait<=2 ----------------
// MODE 0: in_proj (N=2048)   MODE 1: gru_ih   MODE 2: out_proj
#define GSTG 4
#define GROWB 80

template<int MODE, int MT, int NT>
__global__ __launch_bounds__(256,3) void k_gemm(const float* __restrict__ bias,
                                                const float* __restrict__ resid,
                                                float* __restrict__ outf,
                                                int mOff){
    const uint8_t* __restrict__ A;
    const uint8_t* __restrict__ Bw;
    constexpr int K = (MODE==0) ? 512 : 1024;
    if constexpr (MODE==0){ A = g_xn8;   Bw = g_wA8; }
    if constexpr (MODE==1){ A = g_xc8;   Bw = g_wG8; }
    if constexpr (MODE==2){ A = g_ymid8; Bw = g_wO8; }

    constexpr int ASTG_B = MT*GROWB;
    constexpr int STG    = (MT+NT)*GROWB;
    constexpr int NMT = MT/32;
    constexpr int NNT = NT/32;

    extern __shared__ __align__(16) uint8_t dynsm[];
    const unsigned dsm = smem_u32(dynsm);

    const int tid  = threadIdx.x;
    const int lane = tid & 31, warp = tid >> 5;
    const int wm = warp >> 2, wn = warp & 3;
    const int mBlk = mOff + blockIdx.y * MT, nBlk = blockIdx.x * NT;

    unsigned acc[NMT][NNT][2];
    #pragma unroll
    for (int mt=0;mt<NMT;mt++)
        #pragma unroll
        for (int nt=0;nt<NNT;nt++){ acc[mt][nt][0]=0u; acc[mt][nt][1]=0u; }

    constexpr int nKB = K >> 6;
    const int lrow = tid >> 2;
    const int lch  = tid & 3;

    // precomputed ldmatrix fragment offsets (stage-relative)
    unsigned offA[NMT], offB[NNT];
    #pragma unroll
    for (int mt=0;mt<NMT;mt++)
        offA[mt] = (wm*(MT/2) + mt*16 + (lane&15))*GROWB + (lane>>4)*16;
    #pragma unroll
    for (int nt=0;nt<NNT;nt++)
        offB[nt] = ASTG_B + (wn*(NT/4) + nt*8 + (lane&7))*GROWB + ((lane>>3)&1)*16;

    auto prefetch = [&](int kb, int s){
        const int ko = kb*64;
        const unsigned base = dsm + s*STG;
        #pragma unroll
        for (int j=0;j<MT/64;j++){
            int row = lrow + 64*j;
            cp16(base + row*GROWB + lch*16, A + (size_t)(mBlk+row)*K + ko + lch*16);
        }
        #pragma unroll
        for (int j=0;j<NT/64;j++){
            int row = lrow + 64*j;
            cp16(base + ASTG_B + row*GROWB + lch*16, Bw + (size_t)(nBlk+row)*K + ko + lch*16);
        }
        cp_commit();
    };

    prefetch(0, 0);
    prefetch(1, 1);
    prefetch(2, 2);

    int s = 0;
    for (int kb = 0; kb < nKB; kb++){
        cp_wait2();
        __syncthreads();
        int pf = kb + 3;
        if (pf < nKB){
            int sp = s + 3; if (sp >= GSTG) sp -= GSTG;
            prefetch(pf, sp);
        } else {
            cp_commit();
        }

        const unsigned Sb = dsm + s*STG;
        #pragma unroll
        for (int ks=0;ks<2;ks++){
            unsigned a[NMT][4], b[NNT][2];
            #pragma unroll
            for (int mt=0;mt<NMT;mt++)
                ldm_x4(a[mt][0],a[mt][1],a[mt][2],a[mt][3], Sb + offA[mt] + ks*32);
            #pragma unroll
            for (int nt=0;nt<NNT;nt++)
                ldm_x2(b[nt][0],b[nt][1], Sb + offB[nt] + ks*32);
            #pragma unroll
            for (int mt=0;mt<NMT;mt++)
                #pragma unroll
                for (int nt=0;nt<NNT;nt++)
                    mma_fp8_h(acc[mt][nt], a[mt][0],a[mt][1],a[mt][2],a[mt][3], b[nt][0],b[nt][1]);
        }
        s = (s==GSTG-1) ? 0 : s+1;
    }

    // epilogue
    #pragma unroll
    for (int mt=0;mt<NMT;mt++){
        #pragma unroll
        for (int nt=0;nt<NNT;nt++){
            int rowb = mBlk + wm*(MT/2) + mt*16 + (lane>>2);
            int col  = nBlk + wn*(NT/4) + nt*8 + (lane&3)*2;
            #pragma unroll
            for (int half=0; half<2; half++){
                int r = rowb + half*8;
                __half2 hv = *reinterpret_cast<__half2*>(&acc[mt][nt][half]);
                float v0 = __low2float(hv), v1 = __high2float(hv);
                if constexpr (MODE==0){
                    v0 = fmaf(v0, INV0, __ldg(bias + col));
                    v1 = fmaf(v1, INV0, __ldg(bias + col + 1));
                    if (col < 1024){
                        *(unsigned short*)&g_xin8[(size_t)r*1024 + col] =
                            pk8(v0*SCALE_XI, v1*SCALE_XI);
                    } else {
                        *(unsigned short*)&g_siluz8[(size_t)r*1024 + col-1024] =
                            pk8(silu_fast(v0)*SCALE_XI, silu_fast(v1)*SCALE_XI);
                    }
                }
                if constexpr (MODE==1){
                    if (col < GQ){
                        g_xg[(size_t)r*GQ + col]   = fmaf(v0, INV1, __ldg(bias + col));
                        g_xg[(size_t)r*GQ + col+1] = fmaf(v1, INV1, __ldg(bias + col + 1));
                    }
                }
                if constexpr (MODE==2){
                    size_t o = (size_t)r*512 + col;
                    float2 rr = *(const float2*)&resid[o];
                    float2 ov;
                    ov.x = fmaf(v0, INV2, __ldg(bias + col))     + rr.x;
                    ov.y = fmaf(v1, INV2, __ldg(bias + col + 1)) + rr.y;
                    *(float2*)&outf[o] = ov;
                }
            }
        }
    }
}

// ---------------- depthwise conv1d (k=3, pad=1) + SiLU, half grid ----------------
__global__ __launch_bounds__(256) void k_conv(const float* __restrict__ cw, const float* __restrict__ cb,
                                              int mOff){
    const int tid = threadIdx.x;
    const int g = tid & 127;
    const int e0 = g*8;
    float wreg[24]; float breg[8];
    {
        const float4* wp = (const float4*)(cw + e0*3);
        #pragma unroll
        for (int j=0;j<6;j++){
            float4 t = __ldg(wp + j);
            wreg[4*j]  =t.x*(1.f/SCALE_XI); wreg[4*j+1]=t.y*(1.f/SCALE_XI);
            wreg[4*j+2]=t.z*(1.f/SCALE_XI); wreg[4*j+3]=t.w*(1.f/SCALE_XI);
        }
        const float4* bp = (const float4*)(cb + e0);
        float4 t0 = __ldg(bp), t1 = __ldg(bp+1);
        breg[0]=t0.x;breg[1]=t0.y;breg[2]=t0.z;breg[3]=t0.w;
        breg[4]=t1.x;breg[5]=t1.y;breg[6]=t1.z;breg[7]=t1.w;
    }
    const uint2* base = (const uint2*)g_xin8;
    uint2 zz; zz.x=zz.y=0u;

    #pragma unroll
    for (int it=0; it<8; it++){
        int v = blockIdx.x*2048 + it*256 + tid;
        int m = mOff + (v >> 7);
        int l = m & (LQ-1);
        size_t idx = (size_t)m*128 + g;
        uint2 mid2 = base[idx];
        uint2 lf2 = (l > 0)      ? base[idx-128] : zz;
        uint2 rt2 = (l < LQ-1)   ? base[idx+128] : zz;

        float fm[8], fl[8], fr[8];
        up8x4(mid2.x, fm); up8x4(mid2.y, fm+4);
        up8x4(lf2.x,  fl); up8x4(lf2.y,  fl+4);
        up8x4(rt2.x,  fr); up8x4(rt2.y,  fr+4);

        unsigned short outp[4];
        #pragma unroll
        for (int j=0;j<4;j++){
            int jj = 2*j;
            float val0 = fmaf(wreg[jj*3+0], fl[jj],   fmaf(wreg[jj*3+1], fm[jj],   fmaf(wreg[jj*3+2], fr[jj],   breg[jj])));
            float val1 = fmaf(wreg[jj*3+3], fl[jj+1], fmaf(wreg[jj*3+4], fm[jj+1], fmaf(wreg[jj*3+5], fr[jj+1], breg[jj+1])));
            outp[j] = pk8(silu_fast(val0)*SCALE_XC, silu_fast(val1)*SCALE_XC);
        }
        uint2 pack; pack.x = (unsigned)outp[0] | ((unsigned)outp[1]<<16);
        pack.y = (unsigned)outp[2] | ((unsigned)outp[3]<<16);
        *(uint2*)&g_xc8[(size_t)m*EQ + e0] = pack;
    }
}

// ---------------- GRU: chunked-parallel scan (per-batch offset) ----------------
__device__ __forceinline__ float dot16(const float (&w)[16], const float (&h)[16]){
    float a0=0.f,a1=0.f,a2=0.f,a3=0.f,a4=0.f,a5=0.f,a6=0.f,a7=0.f;
    a0=fmaf(w[0],h[0],a0);   a1=fmaf(w[1],h[1],a1);   a2=fmaf(w[2],h[2],a2);   a3=fmaf(w[3],h[3],a3);
    a4=fmaf(w[4],h[4],a4);   a5=fmaf(w[5],h[5],a5);   a6=fmaf(w[6],h[6],a6);   a7=fmaf(w[7],h[7],a7);
    a0=fmaf(w[8],h[8],a0);   a1=fmaf(w[9],h[9],a1);   a2=fmaf(w[10],h[10],a2); a3=fmaf(w[11],h[11],a3);
    a4=fmaf(w[12],h[12],a4); a5=fmaf(w[13],h[13],a5); a6=fmaf(w[14],h[14],a6); a7=fmaf(w[15],h[15],a7);
    return ((a0+a1)+(a2+a3)) + ((a4+a5)+(a6+a7));
}

__global__ __launch_bounds__(32) void k_gru(const float* __restrict__ Whh,
                                            const float* __restrict__ bhh,
                                            int bOff){
    const int b = bOff + blockIdx.x;
    const int c = blockIdx.y;
    const int lane = threadIdx.x;
    __shared__ float sh[32*GQ];

    float Wr[16], Wz[16], Wn[16];
    float br=0.f, bz=0.f, bn=0.f;
    if (lane < 16){
        #pragma unroll
        for (int k=0;k<16;k++){
            Wr[k] = Whh[lane*16 + k];
            Wz[k] = Whh[(16+lane)*16 + k];
            Wn[k] = Whh[(32+lane)*16 + k];
        }
        br = bhh[lane]; bz = bhh[16+lane]; bn = bhh[32+lane];
    } else {
        #pragma unroll
        for (int k=0;k<16;k++){ Wr[k]=0.f; Wz[k]=0.f; Wn[k]=0.f; }
    }

    float h[16];
    #pragma unroll
    for (int k=0;k<16;k++) h[k] = 0.f;
    float hi = 0.f;

    const int start  = c * GRU_CHUNK;
    const int wstart = (c == 0) ? 0 : (start - GRU_WARM);
    const int nsteps = (start + GRU_CHUNK) - wstart;
    const int n32    = nsteps >> 5;

    const float* xb = g_xg + ((size_t)b*LQ + wstart) * GQ;
    float*       hb = g_h  + (size_t)b*LQ*SQ;

    for (int j = 0; j < n32; j++){
        __syncwarp();
        const float4* src = (const float4*)(xb + (size_t)j*32*GQ);
        float4* dst = (float4*)sh;
        #pragma unroll
        for (int q=0;q<12;q++) dst[lane + 32*q] = src[lane + 32*q];
        __syncwarp();
        #pragma unroll 4
        for (int t=0;t<32;t++){
            const float* sp = sh + t*GQ;
            float xr=0.f, xz=0.f, xn=0.f;
            if (lane < 16){ xr = sp[lane]; xz = sp[16+lane]; xn = sp[32+lane]; }
            float hr = dot16(Wr, h) + br;
            float hz = dot16(Wz, h) + bz;
            float hn = dot16(Wn, h) + bn;
            float r  = sigmoid_fast(xr + hr);
            float z  = sigmoid_fast(xz + hz);
            float n  = tanh_fast(fmaf(r, hn, xn));
            float hnew = fmaf(z, hi - n, n);
            #pragma unroll
            for (int k=0;k<16;k++) h[k] = __shfl_sync(0xffffffffu, hnew, k);
            hi = hnew;
            int tg = wstart + j*32 + t;
            if (lane < 16 && tg >= start) hb[(size_t)tg*SQ + lane] = hnew;
        }
    }
}

// ---------------- ssm_proj (K=16) + gate by silu(z) -> e4m3, half grid ----------------
__global__ __launch_bounds__(256) void k_ssm(const float* __restrict__ W, const float* __restrict__ bias,
                                             int mOff){
    int v = blockIdx.x*blockDim.x + threadIdx.x;
    if (v >= MH*(EQ/8)) return;
    int e8 = v & 127;
    int m  = mOff + (v >> 7);
    int e0 = e8*8;

    float h[16];
    {
        const float4* hv = (const float4*)(g_h + (size_t)m*SQ);
        #pragma unroll
        for (int j=0;j<4;j++){
            float4 t = __ldg(hv + j);
            h[4*j]=t.x; h[4*j+1]=t.y; h[4*j+2]=t.z; h[4*j+3]=t.w;
        }
    }
    uint2 sz2 = *(const uint2*)&g_siluz8[(size_t)m*EQ + e0];
    float szf[8];
    up8x4(sz2.x, szf); up8x4(sz2.y, szf+4);

    unsigned short outp[4];
    #pragma unroll
    for (int j=0;j<4;j++){
        float o[2];
        #pragma unroll
        for (int q=0;q<2;q++){
            int e = e0 + 2*j + q;
            const float4* wr = (const float4*)(W + (size_t)e*SQ);
            float acc = __ldg(bias + e);
            #pragma unroll
            for (int p=0;p<4;p++){
                float4 w4 = __ldg(wr + p);
                acc = fmaf(w4.x, h[4*p],   acc);
                acc = fmaf(w4.y, h[4*p+1], acc);
                acc = fmaf(w4.z, h[4*p+2], acc);
                acc = fmaf(w4.w, h[4*p+3], acc);
            }
            o[q] = acc;
        }
        outp[j] = pk8(o[0]*szf[2*j]*(SCALE_YM/SCALE_XI), o[1]*szf[2*j+1]*(SCALE_YM/SCALE_XI));
    }
    uint2 pack; pack.x = (unsigned)outp[0] | ((unsigned)outp[1]<<16);
    pack.y = (unsigned)outp[2] | ((unsigned)outp[3]<<16);
    *(uint2*)&g_ymid8[(size_t)m*EQ + e0] = pack;
}

// ---------------- launch: two batch-half pipelines on two streams ----------------
extern "C" void kernel_launch(void* const* d_in, const int* in_sizes, int n_in,
                              void* d_out, int out_size){
    const float* x        = (const float*)d_in[0];
    const float* norm_w   = (const float*)d_in[1];
    const float* norm_b   = (const float*)d_in[2];
    const float* in_proj_w= (const float*)d_in[3];
    const float* in_proj_b= (const float*)d_in[4];
    const float* conv_w   = (const float*)d_in[5];
    const float* conv_b   = (const float*)d_in[6];
    const float* gru_w_ih = (const float*)d_in[7];
    const float* gru_w_hh = (const float*)d_in[8];
    const float* gru_b_ih = (const float*)d_in[9];
    const float* gru_b_hh = (const float*)d_in[10];
    const float* ssm_w    = (const float*)d_in[11];
    const float* ssm_b    = (const float*)d_in[12];
    const float* out_w    = (const float*)d_in[13];
    const float* out_b    = (const float*)d_in[14];
    float* out = (float*)d_out;

    const int SM0 = GSTG*(64+128)*GROWB;   // 61440
    const int SM1 = GSTG*(64+64)*GROWB;    // 40960
    const int SM2 = GSTG*(64+128)*GROWB;   // 61440

    static cudaStream_t s1 = nullptr;
    static cudaEvent_t evF = nullptr, evJ = nullptr;
    static bool init_done = false;
    if (!init_done){
        cudaFuncSetAttribute(k_gemm<0,64,128>, cudaFuncAttributeMaxDynamicSharedMemorySize, SM0);
        cudaFuncSetAttribute(k_gemm<1,64,64>,  cudaFuncAttributeMaxDynamicSharedMemorySize, SM1);
        cudaFuncSetAttribute(k_gemm<2,64,128>, cudaFuncAttributeMaxDynamicSharedMemorySize, SM2);
        cudaStreamCreateWithFlags(&s1, cudaStreamNonBlocking);
        cudaEventCreateWithFlags(&evF, cudaEventDisableTiming);
        cudaEventCreateWithFlags(&evJ, cudaEventDisableTiming);
        init_done = true;
    }

    const int NCVT4 = (2048*512 + 128*1024 + 512*1024)/4;
    k_convert_all<<<(NCVT4+255)/256, 256>>>(in_proj_w, gru_w_ih, out_w);

    // fork: stream s1 runs the second batch half
    cudaEventRecord(evF, 0);
    cudaStreamWaitEvent(s1, evF, 0);

    // ---- half 0 on main stream ----
    k_ln<<<MH, 128>>>(x, norm_w, norm_b, 0);
    k_gemm<0,64,128><<<dim3(2048/128, MH/64), 256, SM0>>>(in_proj_b, nullptr, nullptr, 0);
    k_conv<<<512, 256>>>(conv_w, conv_b, 0);
    k_gemm<1,64,64><<<dim3(1, MH/64), 256, SM1>>>(gru_b_ih, nullptr, nullptr, 0);
    k_gru<<<dim3(BH, GRU_NC), 32>>>(gru_w_hh, gru_b_hh, 0);
    k_ssm<<<(MH*(EQ/8)+255)/256, 256>>>(ssm_w, ssm_b, 0);
    k_gemm<2,64,128><<<dim3(512/128, MH/64), 256, SM2>>>(out_b, x, out, 0);

    // ---- half 1 on side stream ----
    k_ln<<<MH, 128, 0, s1>>>(x, norm_w, norm_b, MH);
    k_gemm<0,64,128><<<dim3(2048/128, MH/64), 256, SM0, s1>>>(in_proj_b, nullptr, nullptr, MH);
    k_conv<<<512, 256, 0, s1>>>(conv_w, conv_b, MH);
    k_gemm<1,64,64><<<dim3(1, MH/64), 256, SM1, s1>>>(gru_b_ih, nullptr, nullptr, MH);
    k_gru<<<dim3(BH, GRU_NC), 32, 0, s1>>>(gru_w_hh, gru_b_hh, BH);
    k_ssm<<<(MH*(EQ/8)+255)/256, 256, 0, s1>>>(ssm_w, ssm_b, MH);
    k_gemm<2,64,128><<<dim3(512/128, MH/64), 256, SM2, s1>>>(out_b, x, out, MH);

    // join
    cudaEventRecord(evJ, s1);
    cudaStreamWaitEvent(0, evJ, 0);
}